// round 8
// baseline (speedup 1.0000x reference)
#include <cuda_runtime.h>
#include <cuda_fp16.h>
#include <math.h>
#include <stdint.h>

#define BATCH 65536
#define HID   4096
#define RDIM  256
#define EXP   64
#define KCH   64
#define NCH_X 64              // gemm K-chunks
#define NCH_T 72              // total chunks (gemm 64 + router 8)

#define WSCALE   64.0f
#define WUNSCALE 0.015625f

// ------------------------- device scratch -------------------------
__device__ uint4 g_Bhi[2 * 64 * 1024];   // [nb][chunk] 16KB swizzled tiles (Wp*64) hi
__device__ uint4 g_Blo[2 * 64 * 1024];
__device__ uint4 g_Rhi[16 * 1024];       // [nb][chunk 0..7] ([A;Bm]*64) hi
__device__ uint4 g_Rlo[16 * 1024];

// ------------------------- helpers -------------------------
__device__ __forceinline__ uint32_t smem_u32(const void* p) {
    uint32_t a;
    asm("{ .reg .u64 t; cvta.to.shared.u64 t, %1; cvt.u32.u64 %0, t; }" : "=r"(a) : "l"(p));
    return a;
}
__device__ __forceinline__ uint32_t cvt_f16x2(float a, float b) {
    uint32_t r;
    asm("cvt.rn.f16x2.f32 %0, %1, %2;" : "=r"(r) : "f"(b), "f"(a));
    return r;
}
__device__ __forceinline__ void split2(float a, float b, uint32_t& hi, uint32_t& lo) {
    hi = cvt_f16x2(a, b);
    __half2 hh = *reinterpret_cast<__half2*>(&hi);
    float ha = __low2float(hh);
    float hb = __high2float(hh);
    lo = cvt_f16x2(a - ha, b - hb);
}
__device__ __forceinline__ void ldsm4(uint32_t* r, uint32_t addr) {
    asm volatile("ldmatrix.sync.aligned.m8n8.x4.shared.b16 {%0,%1,%2,%3}, [%4];"
        : "=r"(r[0]), "=r"(r[1]), "=r"(r[2]), "=r"(r[3]) : "r"(addr));
}
__device__ __forceinline__ void mma_f16(float* d, const uint32_t* a, const uint32_t* b) {
    asm volatile("mma.sync.aligned.m16n8k16.row.col.f32.f16.f16.f32 "
        "{%0,%1,%2,%3}, {%4,%5,%6,%7}, {%8,%9}, {%0,%1,%2,%3};"
        : "+f"(d[0]), "+f"(d[1]), "+f"(d[2]), "+f"(d[3])
        : "r"(a[0]), "r"(a[1]), "r"(a[2]), "r"(a[3]), "r"(b[0]), "r"(b[1]));
}
__device__ __forceinline__ void cpasync16(uint32_t dst, const void* src) {
    asm volatile("cp.async.cg.shared.global [%0], [%1], 16;" :: "r"(dst), "l"(src));
}
__device__ __forceinline__ void cpcommit() { asm volatile("cp.async.commit_group;" ::: "memory"); }
template<int N> __device__ __forceinline__ void cpwait() {
    asm volatile("cp.async.wait_group %0;" :: "n"(N) : "memory");
}

// ============================================================================
// Prep: Wp [4096,256] fp32 *64 -> f16 hi/lo transposed [n][k] SW128 tiles
// ============================================================================
__global__ void prep_B_kernel(const float* __restrict__ Wp)
{
    int idx = blockIdx.x * 256 + threadIdx.x;
    int n  = idx & 255;
    int kp = idx >> 8;
    int k0 = kp * 2;
    int c  = k0 >> 6;
    int kl = k0 & 63;
    int nb = n >> 7;
    int r  = n & 127;
    float f0 = Wp[(size_t)k0 * RDIM + n] * WSCALE;
    float f1 = Wp[(size_t)(k0 + 1) * RDIM + n] * WSCALE;
    uint32_t hi, lo;
    split2(f0, f1, hi, lo);
    uint32_t off = (uint32_t)(r * 128 + kl * 2);
    off ^= (off >> 3) & 0x70;
    size_t tile = (size_t)(nb * 64 + c) * 16384;
    *(uint32_t*)((char*)g_Bhi + tile + off) = hi;
    *(uint32_t*)((char*)g_Blo + tile + off) = lo;
}

// ============================================================================
// Prep: [A;Bm] (512x256) fp32 *64 -> f16 hi/lo transposed [n][k] SW128 tiles
// ============================================================================
__global__ void prep_R_kernel(const float* __restrict__ Am, const float* __restrict__ Bmm)
{
    int idx = blockIdx.x * 256 + threadIdx.x;
    int n  = idx & 255;
    int kp = idx >> 8;
    int k0 = kp * 2;
    float f0, f1;
    if (k0 < RDIM) {
        f0 = Am[(size_t)k0 * RDIM + n];
        f1 = Am[(size_t)(k0 + 1) * RDIM + n];
    } else {
        f0 = Bmm[(size_t)(k0 - RDIM) * RDIM + n];
        f1 = Bmm[(size_t)(k0 + 1 - RDIM) * RDIM + n];
    }
    uint32_t hi, lo;
    split2(f0 * WSCALE, f1 * WSCALE, hi, lo);
    int c  = k0 >> 6;
    int kl = k0 & 63;
    int nb = n >> 7;
    int r  = n & 127;
    uint32_t off = (uint32_t)(r * 128 + kl * 2);
    off ^= (off >> 3) & 0x70;
    size_t tile = (size_t)(nb * 8 + c) * 16384;
    *(uint32_t*)((char*)g_Rhi + tile + off) = hi;
    *(uint32_t*)((char*)g_Rlo + tile + off) = lo;
}

// ============================================================================
// FUSED kernel: per CTA (64 rows):
//   phase 1 (chunks 0..63):  xp = x @ Wp + bp  -> fp16 hi/lo into smem xp tiles
//   phase 2 (chunks 64..71): ut = [h|xp] @ [A;Bm]  (A from h-staging / xp smem)
//   then CfC -> hnt, logits = h_new @ Wg + bg, temporal bias, top-2, softmax.
// 256 threads, 8 warps, warp tile 32(M) x 64(N).
// smem layout (bytes):
//   0      tau   (1024)
//   1024   bp    (1024)
//   2048   bg    (256)
//   2304   A stages: 2 x 16384 (hi 8K + lo 8K)      -> 35072
//   35072  B stages: 2 x 65536 (hi 32K + lo 32K)    -> 166144
//   166144 xp: 4 tiles x 16384 (hi 8K + lo 8K)      -> 231680
// epilogue overlay (over A+B stages, after mainloop):
//   2304   hnt[256][68] f32 (69632) -> 71936
//   71936  Wgs[256][64] f32 (65536) -> 137472
//   137472 lg[64][68]   f32 (17408) -> 154880
// ============================================================================
#define F_TAU     0
#define F_BP      1024
#define F_BG      2048
#define F_AST(s)  (2304 + (s) * 16384)
#define F_BST(s)  (35072 + (s) * 65536)
#define F_XP      166144
#define F_SMEM    231680
#define F_HNT     2304
#define F_WGS     71936
#define F_LG      137472

__global__ void __launch_bounds__(256, 1)
fused_kernel(const float* __restrict__ x, const float* __restrict__ h,
             const int* __restrict__ prev_sel, const float* __restrict__ tau,
             const float* __restrict__ bp, const float* __restrict__ Wg,
             const float* __restrict__ bg, float* __restrict__ out)
{
    extern __shared__ __align__(1024) char sm[];
    const uint32_t sb = smem_u32(sm);
    float* staus = (float*)(sm + F_TAU);
    float* sbp   = (float*)(sm + F_BP);
    float* sbg   = (float*)(sm + F_BG);
    const int tid  = threadIdx.x;
    const int lane = tid & 31;
    const int wid  = tid >> 5;           // 0..7
    const int wm   = wid >> 2;           // 2 M groups x 32 rows
    const int wn   = wid & 3;            // 4 N groups x 64 cols
    const size_t m0 = (size_t)blockIdx.x * 64;

    staus[tid] = tau[tid];
    sbp[tid]   = bp[tid];
    if (tid < EXP) sbg[tid] = bg[tid];

    // ldmatrix lane addressing
    const int j = lane >> 3;
    const int a_rloc = (lane & 7) + (j & 1) * 8;
    const int a_kadd = (j >> 1) * 16;
    const int a_row0 = wm * 32 + a_rloc;
    const uint32_t a_sw = (uint32_t)((a_row0 & 7) << 4);
    const int b_nloc = (lane & 7) + (j >> 1) * 8;
    const int b_kadd = (j & 1) * 16;
    const uint32_t b_sw = (uint32_t)((lane & 7) << 4);

    // A loader: 64 rows x 16 float4; rows r0+16i (i<4), q = float4 col
    const int r0 = tid >> 4;
    const int q  = tid & 15;
    const uint32_t soff0 = (uint32_t)(r0 * 128 + ((q * 8) ^ ((r0 & 7) << 4)));

    float acc[2][8][4];
#pragma unroll
    for (int a = 0; a < 2; a++)
#pragma unroll
        for (int b = 0; b < 8; b++)
#pragma unroll
            for (int d = 0; d < 4; d++) acc[a][b][d] = 0.0f;

    float4 af[4];

    auto gloadA = [&](int cc) {
        if (cc < NCH_X) {
            const float* src = x + (m0 + r0) * HID + cc * KCH + q * 4;
#pragma unroll
            for (int i = 0; i < 4; i++)
                af[i] = *(const float4*)(src + (size_t)i * 16 * HID);
        } else {
            const float* src = h + (m0 + r0) * RDIM + (cc - NCH_X) * KCH + q * 4;
#pragma unroll
            for (int i = 0; i < 4; i++)
                af[i] = *(const float4*)(src + (size_t)i * 16 * RDIM);
        }
    };
    auto sstoreA = [&](int s) {
        char* dst = sm + F_AST(s);
#pragma unroll
        for (int i = 0; i < 4; i++) {
            uint32_t h01, l01, h23, l23;
            split2(af[i].x, af[i].y, h01, l01);
            split2(af[i].z, af[i].w, h23, l23);
            uint32_t off = soff0 + i * 2048;
            *(uint2*)(dst + off)        = make_uint2(h01, h23);
            *(uint2*)(dst + 8192 + off) = make_uint2(l01, l23);
        }
    };
    auto cpB = [&](int cc, int s) {
        uint32_t dst = sb + F_BST(s);
#pragma unroll
        for (int i = 0; i < 8; i++) {
            int e = tid + i * 256;               // 0..2047 over [nb(2)][1024]
            int nb = e >> 10, jj = e & 1023;
            const uint4* srcH;
            const uint4* srcL;
            if (cc < NCH_X) {
                srcH = g_Bhi + (size_t)(nb * 64 + cc) * 1024 + jj;
                srcL = g_Blo + (size_t)(nb * 64 + cc) * 1024 + jj;
            } else {
                srcH = g_Rhi + (size_t)(nb * 8 + (cc - NCH_X)) * 1024 + jj;
                srcL = g_Rlo + (size_t)(nb * 8 + (cc - NCH_X)) * 1024 + jj;
            }
            cpasync16(dst + e * 16, srcH);
            cpasync16(dst + 32768 + e * 16, srcL);
        }
        cpcommit();
    };
    auto compute = [&](uint32_t aTile, uint32_t bStage) {
        const uint32_t aBase = aTile + a_row0 * 128;
#pragma unroll
        for (int ks = 0; ks < 4; ks++) {
            const uint32_t kb = ks * 32;
            const uint32_t akt = (kb + a_kadd) ^ a_sw;
            uint32_t aH[2][4], aL[2][4];
            ldsm4(aH[0], aBase + akt);
            ldsm4(aH[1], aBase + 2048 + akt);
            ldsm4(aL[0], aBase + 8192 + akt);
            ldsm4(aL[1], aBase + 8192 + 2048 + akt);
            const uint32_t bkt = (kb + b_kadd) ^ b_sw;
#pragma unroll
            for (int p = 0; p < 4; p++) {
                uint32_t rowb = (uint32_t)((wn * 64 + p * 16 + b_nloc) * 128);
                uint32_t rh[4], rl[4];
                ldsm4(rh, bStage + rowb + bkt);
                ldsm4(rl, bStage + 32768 + rowb + bkt);
#pragma unroll
                for (int mt = 0; mt < 2; mt++) {
                    mma_f16(acc[mt][2 * p],     aH[mt], rh);
                    mma_f16(acc[mt][2 * p],     aH[mt], rl);
                    mma_f16(acc[mt][2 * p],     aL[mt], rh);
                    mma_f16(acc[mt][2 * p + 1], aH[mt], rh + 2);
                    mma_f16(acc[mt][2 * p + 1], aH[mt], rl + 2);
                    mma_f16(acc[mt][2 * p + 1], aL[mt], rh + 2);
                }
            }
        }
    };

    // prologue
    cpB(0, 0);
    gloadA(0);
    sstoreA(0);
    gloadA(1);

    for (int c = 0; c < NCH_T; c++) {
        cpwait<0>();
        __syncthreads();
        if (c < NCH_T - 1) cpB(c + 1, (c + 1) & 1);
        uint32_t aTile = (c < 68) ? (sb + F_AST(c & 1))
                                  : (sb + F_XP + (c - 68) * 16384);
        compute(aTile, sb + F_BST(c & 1));
        if (c < 67) sstoreA((c + 1) & 1);
        if (c < 66) gloadA(c + 2);

        if (c == NCH_X - 1) {
            // gemm done: xp = acc*2^-6 + bp -> fp16 hi/lo into smem xp tiles
            char* xbase = sm + F_XP + wn * 16384;
#pragma unroll
            for (int mt = 0; mt < 2; mt++) {
#pragma unroll
                for (int nt = 0; nt < 8; nt++) {
                    int rowl = wm * 32 + mt * 16 + (lane >> 2);
                    int kl   = nt * 8 + (lane & 3) * 2;       // within 64-k tile
                    int col  = wn * 64 + kl;
                    float b0 = sbp[col], b1 = sbp[col + 1];
                    float v0 = acc[mt][nt][0] * WUNSCALE + b0;
                    float v1 = acc[mt][nt][1] * WUNSCALE + b1;
                    float v2 = acc[mt][nt][2] * WUNSCALE + b0;
                    float v3 = acc[mt][nt][3] * WUNSCALE + b1;
                    uint32_t h01, l01, h23, l23;
                    split2(v0, v1, h01, l01);
                    split2(v2, v3, h23, l23);
                    uint32_t sw = (uint32_t)((rowl & 7) << 4);
                    uint32_t o0 = (uint32_t)(rowl * 128 + kl * 2) ^ sw;
                    uint32_t o1 = (uint32_t)((rowl + 8) * 128 + kl * 2) ^ sw;
                    *(uint32_t*)(xbase + o0) = h01;
                    *(uint32_t*)(xbase + 8192 + o0) = l01;
                    *(uint32_t*)(xbase + o1) = h23;
                    *(uint32_t*)(xbase + 8192 + o1) = l23;
                    // reset accumulators for router phase
                    acc[mt][nt][0] = acc[mt][nt][1] = acc[mt][nt][2] = acc[mt][nt][3] = 0.0f;
                }
            }
        }
    }
    __syncthreads();   // all warps done with A/B/xp smem before overlay writes

    // ---- CfC epilogue: h_new transposed into hnt[k][r] (stride 68) ----
    {
        float* hnt = (float*)(sm + F_HNT);
#pragma unroll
        for (int mt = 0; mt < 2; mt++) {
            int rloc = wm * 32 + mt * 16 + (lane >> 2);
            size_t grow = m0 + rloc;
#pragma unroll
            for (int nt = 0; nt < 8; nt++) {
                int c0 = wn * 64 + nt * 8 + (lane & 3) * 2;
                float2 h0 = *(const float2*)(h + grow * RDIM + c0);
                float2 h1 = *(const float2*)(h + (grow + 8) * RDIM + c0);
                float t0 = staus[c0], t1 = staus[c0 + 1];
                hnt[c0 * 68 + rloc]           = h0.x + 0.1f * (-h0.x / t0 + tanhf(acc[mt][nt][0] * WUNSCALE));
                hnt[(c0 + 1) * 68 + rloc]     = h0.y + 0.1f * (-h0.y / t1 + tanhf(acc[mt][nt][1] * WUNSCALE));
                hnt[c0 * 68 + rloc + 8]       = h1.x + 0.1f * (-h1.x / t0 + tanhf(acc[mt][nt][2] * WUNSCALE));
                hnt[(c0 + 1) * 68 + rloc + 8] = h1.y + 0.1f * (-h1.y / t1 + tanhf(acc[mt][nt][3] * WUNSCALE));
            }
        }
    }

    // ---- load Wg into smem ----
    {
        float4* wgs4 = (float4*)(sm + F_WGS);
#pragma unroll
        for (int i = 0; i < 16; i++) {
            int f = tid + i * 256;
            wgs4[f] = ((const float4*)Wg)[f];
        }
    }
    __syncthreads();

    // ---- logits = h_new @ Wg + bg  (256 thr: 64 rows x 4 col-groups) ----
    {
        const float* hnt = (float*)(sm + F_HNT);
        float (*Wgs)[64] = (float(*)[64])(sm + F_WGS);
        float (*lg)[68]  = (float(*)[68])(sm + F_LG);
        int r2 = tid & 63;
        int cg = tid >> 6;          // 0..3 -> 16 cols each
        float lacc[16];
#pragma unroll
        for (int jj = 0; jj < 16; jj++) lacc[jj] = sbg[cg * 16 + jj];
#pragma unroll 8
        for (int k = 0; k < RDIM; k++) {
            float a = hnt[k * 68 + r2];
            const float* wrow = &Wgs[k][cg * 16];
            float4 w0 = *(const float4*)(wrow + 0);
            float4 w1 = *(const float4*)(wrow + 4);
            float4 w2 = *(const float4*)(wrow + 8);
            float4 w3 = *(const float4*)(wrow + 12);
            lacc[0]  += a * w0.x;  lacc[1]  += a * w0.y;  lacc[2]  += a * w0.z;  lacc[3]  += a * w0.w;
            lacc[4]  += a * w1.x;  lacc[5]  += a * w1.y;  lacc[6]  += a * w1.z;  lacc[7]  += a * w1.w;
            lacc[8]  += a * w2.x;  lacc[9]  += a * w2.y;  lacc[10] += a * w2.z;  lacc[11] += a * w2.w;
            lacc[12] += a * w3.x;  lacc[13] += a * w3.y;  lacc[14] += a * w3.z;  lacc[15] += a * w3.w;
        }
        float* lrow = &lg[r2][cg * 16];
        *(float4*)(lrow + 0)  = make_float4(lacc[0],  lacc[1],  lacc[2],  lacc[3]);
        *(float4*)(lrow + 4)  = make_float4(lacc[4],  lacc[5],  lacc[6],  lacc[7]);
        *(float4*)(lrow + 8)  = make_float4(lacc[8],  lacc[9],  lacc[10], lacc[11]);
        *(float4*)(lrow + 12) = make_float4(lacc[12], lacc[13], lacc[14], lacc[15]);
    }
    __syncthreads();

    // ---- temporal bias + top-2 + softmax ----
    if (tid < 64) {
        float (*lg)[68] = (float(*)[68])(sm + F_LG);
        size_t grow = m0 + tid;
        int p0 = prev_sel[grow * 2 + 0];
        int p1 = prev_sel[grow * 2 + 1];
        float b1 = -1e30f, b2 = -1e30f;
        int i1 = 0, i2 = 0;
#pragma unroll 8
        for (int e = 0; e < EXP; e++) {
            float v = lg[tid][e];
            if (e == p0 || e == p1) v += 0.1f;
            if (v > b1) { b2 = b1; i2 = i1; b1 = v; i1 = e; }
            else if (v > b2) { b2 = v; i2 = e; }
        }
        float ex = expf(b2 - b1);
        float s  = 1.0f + ex;
        out[grow * 2 + 0] = (float)i1;
        out[grow * 2 + 1] = (float)i2;
        out[2 * (size_t)BATCH + grow * 2 + 0] = 1.0f / s;
        out[2 * (size_t)BATCH + grow * 2 + 1] = ex / s;
    }
}

extern "C" void kernel_launch(void* const* d_in, const int* in_sizes, int n_in,
                              void* d_out, int out_size)
{
    const float* x        = (const float*)d_in[0];
    const float* h        = (const float*)d_in[1];
    const int*   prev_sel = (const int*)d_in[2];
    const float* Wp       = (const float*)d_in[3];
    const float* bp       = (const float*)d_in[4];
    const float* tau      = (const float*)d_in[5];
    const float* Am       = (const float*)d_in[6];
    const float* Bmm      = (const float*)d_in[7];
    const float* Wg       = (const float*)d_in[8];
    const float* bg       = (const float*)d_in[9];
    float* out = (float*)d_out;

    cudaFuncSetAttribute(fused_kernel, cudaFuncAttributeMaxDynamicSharedMemorySize, F_SMEM);

    prep_B_kernel<<<2048, 256>>>(Wp);
    prep_R_kernel<<<256, 256>>>(Am, Bmm);
    fused_kernel<<<BATCH / 64, 256, F_SMEM>>>(x, h, prev_sel, tau, bp, Wg, bg, out);
}

// round 9
// speedup vs baseline: 1.0628x; 1.0628x over previous
#include <cuda_runtime.h>
#include <cuda_fp16.h>
#include <math.h>
#include <stdint.h>

#define BATCH 65536
#define HID   4096
#define RDIM  256
#define EXP   64
#define KCH   64
#define NCHUNK 64

#define WSCALE   64.0f       // weight pre-scale (exact power of 2)
#define WUNSCALE 0.015625f   // 1/64

// ------------------------- device scratch -------------------------
__device__ float g_xproj[BATCH * (size_t)RDIM];     // 64 MB
__device__ uint4 g_Bhi[2 * 64 * 1024];              // 2 MB: [nb][chunk] 16KB swizzled tiles (Wp*64)
__device__ uint4 g_Blo[2 * 64 * 1024];              // 2 MB
__device__ uint4 g_Rhi[16 * 1024];                  // 256 KB: [nb][chunk 0..7] ([A;Bm]*64)
__device__ uint4 g_Rlo[16 * 1024];                  // 256 KB

// ------------------------- helpers -------------------------
__device__ __forceinline__ uint32_t smem_u32(const void* p) {
    uint32_t a;
    asm("{ .reg .u64 t; cvta.to.shared.u64 t, %1; cvt.u32.u64 %0, t; }" : "=r"(a) : "l"(p));
    return a;
}
__device__ __forceinline__ uint32_t cvt_f16x2(float a, float b) {
    uint32_t r;
    asm("cvt.rn.f16x2.f32 %0, %1, %2;" : "=r"(r) : "f"(b), "f"(a));
    return r;
}
__device__ __forceinline__ void split2(float a, float b, uint32_t& hi, uint32_t& lo) {
    hi = cvt_f16x2(a, b);
    __half2 hh = *reinterpret_cast<__half2*>(&hi);
    float ha = __low2float(hh);
    float hb = __high2float(hh);
    lo = cvt_f16x2(a - ha, b - hb);
}
__device__ __forceinline__ void ldsm4(uint32_t* r, uint32_t addr) {
    asm volatile("ldmatrix.sync.aligned.m8n8.x4.shared.b16 {%0,%1,%2,%3}, [%4];"
        : "=r"(r[0]), "=r"(r[1]), "=r"(r[2]), "=r"(r[3]) : "r"(addr));
}
__device__ __forceinline__ void mma_f16(float* d, const uint32_t* a, const uint32_t* b) {
    asm volatile("mma.sync.aligned.m16n8k16.row.col.f32.f16.f16.f32 "
        "{%0,%1,%2,%3}, {%4,%5,%6,%7}, {%8,%9}, {%0,%1,%2,%3};"
        : "+f"(d[0]), "+f"(d[1]), "+f"(d[2]), "+f"(d[3])
        : "r"(a[0]), "r"(a[1]), "r"(a[2]), "r"(a[3]), "r"(b[0]), "r"(b[1]));
}
__device__ __forceinline__ void cpasync16(uint32_t dst, const void* src) {
    asm volatile("cp.async.cg.shared.global [%0], [%1], 16;" :: "r"(dst), "l"(src));
}
__device__ __forceinline__ void cpcommit() { asm volatile("cp.async.commit_group;" ::: "memory"); }
template<int N> __device__ __forceinline__ void cpwait() {
    asm volatile("cp.async.wait_group %0;" :: "n"(N) : "memory");
}

// ============================================================================
// Prep: Wp [4096,256] fp32 *64 -> f16 hi/lo transposed [n][k] SW128 tiles
// ============================================================================
__global__ void prep_B_kernel(const float* __restrict__ Wp)
{
    int idx = blockIdx.x * 256 + threadIdx.x;
    int n  = idx & 255;
    int kp = idx >> 8;
    int k0 = kp * 2;
    int c  = k0 >> 6;
    int kl = k0 & 63;
    int nb = n >> 7;
    int r  = n & 127;
    float f0 = Wp[(size_t)k0 * RDIM + n] * WSCALE;
    float f1 = Wp[(size_t)(k0 + 1) * RDIM + n] * WSCALE;
    uint32_t hi, lo;
    split2(f0, f1, hi, lo);
    uint32_t off = (uint32_t)(r * 128 + kl * 2);
    off ^= (off >> 3) & 0x70;
    size_t tile = (size_t)(nb * 64 + c) * 16384;
    *(uint32_t*)((char*)g_Bhi + tile + off) = hi;
    *(uint32_t*)((char*)g_Blo + tile + off) = lo;
}

// ============================================================================
// Prep: [A;Bm] (512x256) fp32 *64 -> f16 hi/lo transposed [n][k] SW128 tiles
// ============================================================================
__global__ void prep_R_kernel(const float* __restrict__ Am, const float* __restrict__ Bmm)
{
    int idx = blockIdx.x * 256 + threadIdx.x;
    int n  = idx & 255;
    int kp = idx >> 8;
    int k0 = kp * 2;
    float f0, f1;
    if (k0 < RDIM) {
        f0 = Am[(size_t)k0 * RDIM + n];
        f1 = Am[(size_t)(k0 + 1) * RDIM + n];
    } else {
        f0 = Bmm[(size_t)(k0 - RDIM) * RDIM + n];
        f1 = Bmm[(size_t)(k0 + 1 - RDIM) * RDIM + n];
    }
    uint32_t hi, lo;
    split2(f0 * WSCALE, f1 * WSCALE, hi, lo);
    int c  = k0 >> 6;
    int kl = k0 & 63;
    int nb = n >> 7;
    int r  = n & 127;
    uint32_t off = (uint32_t)(r * 128 + kl * 2);
    off ^= (off >> 3) & 0x70;
    size_t tile = (size_t)(nb * 8 + c) * 16384;
    *(uint32_t*)((char*)g_Rhi + tile + off) = hi;
    *(uint32_t*)((char*)g_Rlo + tile + off) = lo;
}

// ============================================================================
// GEMM1 via mma.sync f16 (3-pass hi/lo, PASS-OUTER ordering): x_proj = x@Wp+bp
// CTA: 128(M) x 128(N), grid (512, 2), 256 threads (8 warps, warp tile 32x64)
// ============================================================================
#define AST_OFF(s) (1024 + (s) * 32768)
#define BST_OFF(s) (66560 + (s) * 32768)
#define G1_SMEM 132096

__global__ void __launch_bounds__(256, 1)
gemm1_mma_kernel(const float* __restrict__ x, const float* __restrict__ bp)
{
    extern __shared__ __align__(1024) char sm[];
    const uint32_t sb = smem_u32(sm);
    float* sbp = (float*)sm;
    const int tid  = threadIdx.x;
    const int lane = tid & 31;
    const int wid  = tid >> 5;
    const int wm   = wid & 3;
    const int wn   = wid >> 2;
    const int mb   = blockIdx.x;
    const int ny   = blockIdx.y;
    const size_t m0 = (size_t)mb * 128;

    if (tid < 128) sbp[tid] = bp[ny * 128 + tid];

    const int j = lane >> 3;
    const int a_rloc = (lane & 7) + (j & 1) * 8;
    const int a_kadd = (j >> 1) * 16;
    const int a_row0 = wm * 32 + a_rloc;
    const uint32_t a_xp = (uint32_t)((a_row0 & 7) << 4);
    const int b_nloc = (lane & 7) + (j >> 1) * 8;
    const int b_kadd = (j & 1) * 16;
    const uint32_t b_xp = (uint32_t)((lane & 7) << 4);
    uint32_t bRow[4];
#pragma unroll
    for (int p = 0; p < 4; p++) bRow[p] = (uint32_t)((wn * 64 + p * 16 + b_nloc) * 128);

    const int r0 = tid >> 4;
    const int q  = tid & 15;
    const float* xbase = x + (m0 + r0) * HID + q * 4;
    const uint32_t soff0 = (uint32_t)(r0 * 128 + (((q * 8)) ^ ((r0 & 7) << 4)));

    float acc[2][8][4];
#pragma unroll
    for (int a = 0; a < 2; a++)
#pragma unroll
        for (int b = 0; b < 8; b++)
#pragma unroll
            for (int d = 0; d < 4; d++) acc[a][b][d] = 0.0f;

    float4 af[8];

    auto gloadA = [&](int c) {
#pragma unroll
        for (int i = 0; i < 8; i++)
            af[i] = *(const float4*)(xbase + (size_t)i * 16 * HID + c * KCH);
    };
    auto sstoreA = [&](int s) {
        char* dst = sm + AST_OFF(s);
#pragma unroll
        for (int i = 0; i < 8; i++) {
            uint32_t h01, l01, h23, l23;
            split2(af[i].x, af[i].y, h01, l01);
            split2(af[i].z, af[i].w, h23, l23);
            uint32_t off = soff0 + i * 2048;
            *(uint2*)(dst + off)         = make_uint2(h01, h23);
            *(uint2*)(dst + 16384 + off) = make_uint2(l01, l23);
        }
    };
    auto cpB = [&](int c, int s) {
        const uint4* srcH = g_Bhi + (size_t)(ny * 64 + c) * 1024;
        const uint4* srcL = g_Blo + (size_t)(ny * 64 + c) * 1024;
        uint32_t dst = sb + BST_OFF(s);
#pragma unroll
        for (int i = 0; i < 4; i++) {
            int e = tid + i * 256;
            cpasync16(dst + e * 16, srcH + e);
            cpasync16(dst + 16384 + e * 16, srcL + e);
        }
        cpcommit();
    };
    auto compute = [&](int s) {
        const uint32_t aBase = sb + AST_OFF(s) + a_row0 * 128;
        const uint32_t sBhi  = sb + BST_OFF(s);
#pragma unroll
        for (int ks = 0; ks < 4; ks++) {
            const uint32_t kb = ks * 32;
            const uint32_t akt = (kb + a_kadd) ^ a_xp;
            uint32_t aH[2][4], aL[2][4];
            ldsm4(aH[0], aBase + akt);
            ldsm4(aH[1], aBase + 2048 + akt);
            ldsm4(aL[0], aBase + 16384 + akt);
            ldsm4(aL[1], aBase + 16384 + 2048 + akt);
            const uint32_t bkt = (kb + b_kadd) ^ b_xp;
            uint32_t bH[8][2], bL[8][2];
#pragma unroll
            for (int p = 0; p < 4; p++) {
                uint32_t r[4];
                ldsm4(r, sBhi + bRow[p] + bkt);
                bH[2 * p][0] = r[0]; bH[2 * p][1] = r[1];
                bH[2 * p + 1][0] = r[2]; bH[2 * p + 1][1] = r[3];
                ldsm4(r, sBhi + 16384 + bRow[p] + bkt);
                bL[2 * p][0] = r[0]; bL[2 * p][1] = r[1];
                bL[2 * p + 1][0] = r[2]; bL[2 * p + 1][1] = r[3];
            }
            // PASS-OUTER: same-acc reuse distance = 16 MMAs (RAW chains broken)
#pragma unroll
            for (int mt = 0; mt < 2; mt++)
#pragma unroll
                for (int nt = 0; nt < 8; nt++)
                    mma_f16(acc[mt][nt], aH[mt], bH[nt]);
#pragma unroll
            for (int mt = 0; mt < 2; mt++)
#pragma unroll
                for (int nt = 0; nt < 8; nt++)
                    mma_f16(acc[mt][nt], aH[mt], bL[nt]);
#pragma unroll
            for (int mt = 0; mt < 2; mt++)
#pragma unroll
                for (int nt = 0; nt < 8; nt++)
                    mma_f16(acc[mt][nt], aL[mt], bH[nt]);
        }
    };

    // prologue
    cpB(0, 0);
    gloadA(0);
    sstoreA(0);
    gloadA(1);

    for (int c = 0; c < NCHUNK; c++) {
        cpwait<0>();
        __syncthreads();
        if (c < NCHUNK - 1) cpB(c + 1, (c + 1) & 1);
        compute(c & 1);
        if (c < NCHUNK - 1) sstoreA((c + 1) & 1);
        if (c < NCHUNK - 2) gloadA(c + 2);
    }

    // epilogue: acc * 2^-6 + bp -> g_xproj
#pragma unroll
    for (int mt = 0; mt < 2; mt++) {
#pragma unroll
        for (int nt = 0; nt < 8; nt++) {
            int row  = (int)m0 + wm * 32 + mt * 16 + (lane >> 2);
            int coll = wn * 64 + nt * 8 + (lane & 3) * 2;
            int gcol = ny * 128 + coll;
            float b0 = sbp[coll], b1 = sbp[coll + 1];
            float2 v0 = make_float2(acc[mt][nt][0] * WUNSCALE + b0, acc[mt][nt][1] * WUNSCALE + b1);
            float2 v1 = make_float2(acc[mt][nt][2] * WUNSCALE + b0, acc[mt][nt][3] * WUNSCALE + b1);
            *(float2*)(g_xproj + (size_t)row * RDIM + gcol) = v0;
            *(float2*)(g_xproj + (size_t)(row + 8) * RDIM + gcol) = v1;
        }
    }
}

// ============================================================================
// Router (tensorized, f16 3-pass, PASS-OUTER ordering)
// CTA: M=64 x N=256, K=512 (8 chunks), 512 threads (16 warps, warp tile 16x64)
// ============================================================================
#define R_AST(s)   (2048 + (s) * 16384)
#define R_BST(s)   (34816 + (s) * 65536)
#define R_OFF_HNT  2048
#define R_OFF_WGS  71680
#define R_OFF_LG   137216
#define R_SMEM     165888

__global__ void __launch_bounds__(512, 1)
router_mma_kernel(const float* __restrict__ h, const int* __restrict__ prev_sel,
                  const float* __restrict__ tau,
                  const float* __restrict__ Wg, const float* __restrict__ bg,
                  float* __restrict__ out)
{
    extern __shared__ __align__(1024) char sm[];
    const uint32_t sb = smem_u32(sm);
    float* staus = (float*)sm;
    float* bgs   = (float*)(sm + 1024);
    const int tid  = threadIdx.x;
    const int lane = tid & 31;
    const int wid  = tid >> 5;
    const int wm   = wid & 3;            // 4 M groups x 16 rows
    const int wn   = wid >> 2;           // 4 N groups x 64 cols
    const size_t m0 = (size_t)blockIdx.x * 64;

    if (tid < 256) staus[tid] = tau[tid];
    if (tid >= 256 && tid < 256 + EXP) bgs[tid - 256] = bg[tid - 256];

    const int j = lane >> 3;
    const int a_rloc = (lane & 7) + (j & 1) * 8;
    const int a_kadd = (j >> 1) * 16;
    const int a_row0 = wm * 16 + a_rloc;
    const uint32_t a_xp = (uint32_t)((a_row0 & 7) << 4);
    const int b_nloc = (lane & 7) + (j >> 1) * 8;
    const int b_kadd = (j & 1) * 16;
    const uint32_t b_xp = (uint32_t)((lane & 7) << 4);

    const int r0 = tid >> 4;
    const int q  = tid & 15;

    float acc[8][4];
#pragma unroll
    for (int b = 0; b < 8; b++)
#pragma unroll
        for (int d = 0; d < 4; d++) acc[b][d] = 0.0f;

    float4 af[2];

    auto gloadA = [&](int c) {
        const float* src = (c < 4) ? (h + (m0 + r0) * RDIM + c * KCH + q * 4)
                                   : (g_xproj + (m0 + r0) * RDIM + (c - 4) * KCH + q * 4);
#pragma unroll
        for (int i = 0; i < 2; i++)
            af[i] = *(const float4*)(src + (size_t)i * 32 * RDIM);
    };
    auto sstoreA = [&](int s) {
        char* dst = sm + R_AST(s);
#pragma unroll
        for (int i = 0; i < 2; i++) {
            uint32_t h01, l01, h23, l23;
            split2(af[i].x, af[i].y, h01, l01);
            split2(af[i].z, af[i].w, h23, l23);
            int r = r0 + 32 * i;
            uint32_t off = (uint32_t)(r * 128 + ((q * 8) ^ ((r0 & 7) << 4)));
            *(uint2*)(dst + off)        = make_uint2(h01, h23);
            *(uint2*)(dst + 8192 + off) = make_uint2(l01, l23);
        }
    };
    auto cpB = [&](int c, int s) {
        uint32_t dst = sb + R_BST(s);
#pragma unroll
        for (int i = 0; i < 4; i++) {
            int e = tid + i * 512;
            int nb = e >> 10, jj = e & 1023;
            const uint4* srcH = g_Rhi + (size_t)(nb * 8 + c) * 1024 + jj;
            const uint4* srcL = g_Rlo + (size_t)(nb * 8 + c) * 1024 + jj;
            cpasync16(dst + e * 16, srcH);
            cpasync16(dst + 32768 + e * 16, srcL);
        }
        cpcommit();
    };
    auto compute = [&](int s) {
        const uint32_t aBase  = sb + R_AST(s) + a_row0 * 128;
        const uint32_t hiBase = sb + R_BST(s) + (wn >> 1) * 16384;
        const uint32_t nbase  = (uint32_t)((wn & 1) * 64 + b_nloc);
#pragma unroll
        for (int ks = 0; ks < 4; ks++) {
            const uint32_t kb = ks * 32;
            const uint32_t akt = (kb + a_kadd) ^ a_xp;
            uint32_t aH[4], aL[4];
            ldsm4(aH, aBase + akt);
            ldsm4(aL, aBase + 8192 + akt);
            const uint32_t bkt = (kb + b_kadd) ^ b_xp;
            uint32_t bH[8][2], bL[8][2];
#pragma unroll
            for (int p = 0; p < 4; p++) {
                uint32_t rr[4];
                uint32_t rowb = (nbase + p * 16) * 128;
                ldsm4(rr, hiBase + rowb + bkt);
                bH[2 * p][0] = rr[0]; bH[2 * p][1] = rr[1];
                bH[2 * p + 1][0] = rr[2]; bH[2 * p + 1][1] = rr[3];
                ldsm4(rr, hiBase + 32768 + rowb + bkt);
                bL[2 * p][0] = rr[0]; bL[2 * p][1] = rr[1];
                bL[2 * p + 1][0] = rr[2]; bL[2 * p + 1][1] = rr[3];
            }
            // PASS-OUTER: same-acc reuse distance = 8 MMAs
#pragma unroll
            for (int p = 0; p < 8; p++) mma_f16(acc[p], aH, bH[p]);
#pragma unroll
            for (int p = 0; p < 8; p++) mma_f16(acc[p], aH, bL[p]);
#pragma unroll
            for (int p = 0; p < 8; p++) mma_f16(acc[p], aL, bH[p]);
        }
    };

    // prologue
    cpB(0, 0);
    gloadA(0);
    sstoreA(0);
    gloadA(1);

    for (int c = 0; c < 8; c++) {
        cpwait<0>();
        __syncthreads();
        if (c < 7) cpB(c + 1, (c + 1) & 1);
        compute(c & 1);
        if (c < 7) sstoreA((c + 1) & 1);
        if (c < 6) gloadA(c + 2);
    }
    __syncthreads();

    // ---- CfC epilogue: h_new transposed into hnt[k][r] (stride 68) ----
    {
        float* hnt = (float*)(sm + R_OFF_HNT);
        const int rloc = wm * 16 + (lane >> 2);
        const size_t grow = m0 + rloc;
#pragma unroll
        for (int nt = 0; nt < 8; nt++) {
            int c0 = wn * 64 + nt * 8 + (lane & 3) * 2;
            float2 h0 = *(const float2*)(h + grow * RDIM + c0);
            float2 h1 = *(const float2*)(h + (grow + 8) * RDIM + c0);
            float t0 = staus[c0], t1 = staus[c0 + 1];
            hnt[c0 * 68 + rloc]           = h0.x + 0.1f * (-h0.x / t0 + tanhf(acc[nt][0] * WUNSCALE));
            hnt[(c0 + 1) * 68 + rloc]     = h0.y + 0.1f * (-h0.y / t1 + tanhf(acc[nt][1] * WUNSCALE));
            hnt[c0 * 68 + rloc + 8]       = h1.x + 0.1f * (-h1.x / t0 + tanhf(acc[nt][2] * WUNSCALE));
            hnt[(c0 + 1) * 68 + rloc + 8] = h1.y + 0.1f * (-h1.y / t1 + tanhf(acc[nt][3] * WUNSCALE));
        }
    }

    // ---- load Wg into smem ----
    {
        float4* wgs4 = (float4*)(sm + R_OFF_WGS);
#pragma unroll
        for (int i = 0; i < 8; i++) {
            int f = tid + i * 512;
            wgs4[f] = ((const float4*)Wg)[f];
        }
    }
    __syncthreads();

    // ---- logits = h_new @ Wg + bg ----
    {
        const float* hnt = (float*)(sm + R_OFF_HNT);
        float (*Wgs)[64] = (float(*)[64])(sm + R_OFF_WGS);
        float (*lg)[68]  = (float(*)[68])(sm + R_OFF_LG);
        int r2 = tid & 63;
        int cg = tid >> 6;
        float lacc[8];
#pragma unroll
        for (int jj = 0; jj < 8; jj++) lacc[jj] = bgs[cg * 8 + jj];
#pragma unroll 8
        for (int k = 0; k < RDIM; k++) {
            float a = hnt[k * 68 + r2];
            const float* wrow = &Wgs[k][cg * 8];
            float4 w0 = *(const float4*)(wrow + 0);
            float4 w1 = *(const float4*)(wrow + 4);
            lacc[0] += a * w0.x;  lacc[1] += a * w0.y;  lacc[2] += a * w0.z;  lacc[3] += a * w0.w;
            lacc[4] += a * w1.x;  lacc[5] += a * w1.y;  lacc[6] += a * w1.z;  lacc[7] += a * w1.w;
        }
        float* lrow = &lg[r2][cg * 8];
        *(float4*)(lrow + 0) = make_float4(lacc[0], lacc[1], lacc[2], lacc[3]);
        *(float4*)(lrow + 4) = make_float4(lacc[4], lacc[5], lacc[6], lacc[7]);
    }
    __syncthreads();

    // ---- temporal bias + top-2 + softmax ----
    if (tid < 64) {
        float (*lg)[68] = (float(*)[68])(sm + R_OFF_LG);
        size_t grow = m0 + tid;
        int p0 = prev_sel[grow * 2 + 0];
        int p1 = prev_sel[grow * 2 + 1];
        float b1 = -1e30f, b2 = -1e30f;
        int i1 = 0, i2 = 0;
#pragma unroll 8
        for (int e = 0; e < EXP; e++) {
            float v = lg[tid][e];
            if (e == p0 || e == p1) v += 0.1f;
            if (v > b1) { b2 = b1; i2 = i1; b1 = v; i1 = e; }
            else if (v > b2) { b2 = v; i2 = e; }
        }
        float ex = expf(b2 - b1);
        float s  = 1.0f + ex;
        out[grow * 2 + 0] = (float)i1;
        out[grow * 2 + 1] = (float)i2;
        out[2 * (size_t)BATCH + grow * 2 + 0] = 1.0f / s;
        out[2 * (size_t)BATCH + grow * 2 + 1] = ex / s;
    }
}

extern "C" void kernel_launch(void* const* d_in, const int* in_sizes, int n_in,
                              void* d_out, int out_size)
{
    const float* x        = (const float*)d_in[0];
    const float* h        = (const float*)d_in[1];
    const int*   prev_sel = (const int*)d_in[2];
    const float* Wp       = (const float*)d_in[3];
    const float* bp       = (const float*)d_in[4];
    const float* tau      = (const float*)d_in[5];
    const float* Am       = (const float*)d_in[6];
    const float* Bmm      = (const float*)d_in[7];
    const float* Wg       = (const float*)d_in[8];
    const float* bg       = (const float*)d_in[9];
    float* out = (float*)d_out;

    cudaFuncSetAttribute(gemm1_mma_kernel, cudaFuncAttributeMaxDynamicSharedMemorySize, G1_SMEM);
    cudaFuncSetAttribute(router_mma_kernel, cudaFuncAttributeMaxDynamicSharedMemorySize, R_SMEM);

    prep_B_kernel<<<2048, 256>>>(Wp);
    prep_R_kernel<<<256, 256>>>(Am, Bmm);
    gemm1_mma_kernel<<<dim3(512, 2), 256, G1_SMEM>>>(x, bp);
    router_mma_kernel<<<BATCH / 64, 512, R_SMEM>>>(h, prev_sel, tau, Wg, bg, out);
}